// round 15
// baseline (speedup 1.0000x reference)
#include <cuda_runtime.h>
#include <cuda_fp16.h>
#include <cstdint>

#define B_ 4
#define L_ 2048
#define D_ 512
#define H_ 8
#define E_ 64

// Projected Q/K fp16 [B,H,L,E]; V transposed fp16 [B,H,E,L].
__device__ __align__(256) __half g_qh[B_ * H_ * L_ * E_];
__device__ __align__(256) __half g_kh[B_ * H_ * L_ * E_];
__device__ __align__(256) __half g_vth[B_ * H_ * E_ * L_];
// Unnormalized exp(scores) scratch, fp16:
__device__ __align__(256) __half g_se[(size_t)B_ * H_ * L_ * L_];
// Per-row partial sums of exp(scores): [row_global][col_tile 0..15]
__device__ __align__(256) float g_psum[B_ * H_ * L_ * 16];

// ---------------------------------------------------------------------------
// helpers
// ---------------------------------------------------------------------------
__device__ __forceinline__ uint32_t smem_u32(const void* p) {
    uint32_t a;
    asm("{ .reg .u64 t; cvta.to.shared.u64 t, %1; cvt.u32.u64 %0, t; }"
        : "=r"(a) : "l"(p));
    return a;
}

// pack two fp32 -> fp16x2 (lo, hi)
__device__ __forceinline__ uint32_t f2h2(float lo, float hi) {
    uint32_t r;
    asm("cvt.rn.f16x2.f32 %0, %1, %2;" : "=r"(r) : "f"(hi), "f"(lo));
    return r;
}

// 2^x on packed halfs
__device__ __forceinline__ uint32_t ex2_h2(uint32_t x) {
    uint32_t r;
    asm("ex2.approx.f16x2 %0, %1;" : "=r"(r) : "r"(x));
    return r;
}

// fp16 m16n8k16, fp32 accum
__device__ __forceinline__ void mma_f16(float* d, const uint32_t* a, const uint32_t* b) {
    asm volatile(
        "mma.sync.aligned.m16n8k16.row.col.f32.f16.f16.f32 "
        "{%0,%1,%2,%3}, {%4,%5,%6,%7}, {%8,%9}, {%0,%1,%2,%3};"
        : "+f"(d[0]), "+f"(d[1]), "+f"(d[2]), "+f"(d[3])
        : "r"(a[0]), "r"(a[1]), "r"(a[2]), "r"(a[3]), "r"(b[0]), "r"(b[1]));
}

__device__ __forceinline__ void cp16(uint32_t dst, const void* src) {
    asm volatile("cp.async.cg.shared.global [%0], [%1], 16;"
                 :: "r"(dst), "l"(src) : "memory");
}
#define CP_COMMIT() asm volatile("cp.async.commit_group;" ::: "memory")
#define CP_WAIT(n)  asm volatile("cp.async.wait_group %0;" :: "n"(n) : "memory")

__device__ __forceinline__ void st_cs4(float* p, float4 v) {
    asm volatile("st.global.cs.v4.f32 [%0], {%1, %2, %3, %4};"
                 :: "l"(p), "f"(v.x), "f"(v.y), "f"(v.z), "f"(v.w) : "memory");
}
__device__ __forceinline__ void st_cs_h2(__half* p, uint32_t v) {
    asm volatile("st.global.cs.b32 [%0], %1;" :: "l"(p), "r"(v) : "memory");
}

// ---------------------------------------------------------------------------
// Kernel 1: unified QKV projection via fp16 MMA (fp32 staged, frags converted).
// z=0/1 -> Q/K fp16 [B,H,L,E];  z=2 -> V transposed fp16 [B,H,E,L].
// CTA 128x128, 8 warps (2M x 4N), K=512 in BK=32 chunks, double buffer.
// grid (64, 4, 3), 256 thr.
// ---------------------------------------------------------------------------
static constexpr int PJ_XS = 128 * 36;
static constexpr int PJ_WS = 32 * 136;
static constexpr int PJ_SMEM = (2 * PJ_XS + 2 * PJ_WS) * 4;   // 71680 B

__global__ void __launch_bounds__(256, 2) proj_all(
    const float* __restrict__ X0, const float* __restrict__ X1,
    const float* __restrict__ X2,
    const float* __restrict__ W0, const float* __restrict__ W1,
    const float* __restrict__ W2,
    const float* __restrict__ b0, const float* __restrict__ b1,
    const float* __restrict__ b2)
{
    extern __shared__ float smf[];
    float* Xs = smf;
    float* Ws = smf + 2 * PJ_XS;
    uint32_t sX = smem_u32(Xs), sW = smem_u32(Ws);

    int z = blockIdx.z;
    const float* X = (z == 0) ? X0 : (z == 1) ? X1 : X2;
    const float* W = (z == 0) ? W0 : (z == 1) ? W1 : W2;
    const float* bias = (z == 0) ? b0 : (z == 1) ? b1 : b2;

    int t = threadIdx.x;
    int lane = t & 31, wid = t >> 5;
    int gid = lane >> 2, tg = lane & 3;
    int warpM = wid >> 2, warpN = wid & 3;
    int m0 = blockIdx.x * 128, n0 = blockIdx.y * 128;

    float acc[4][4][4] = {};

    auto stage = [&](int kt, int buf) {
        int k0 = kt * 32;
#pragma unroll
        for (int i = 0; i < 4; i++) {
            int idx = t + i * 256;
            int row = idx >> 3, cc = (idx & 7) * 4;
            cp16(sX + (buf * PJ_XS + row * 36 + cc) * 4,
                 X + (size_t)(m0 + row) * D_ + k0 + cc);
        }
#pragma unroll
        for (int i = 0; i < 4; i++) {
            int idx = t + i * 256;
            int row = idx >> 5, cc = (idx & 31) * 4;
            cp16(sW + (buf * PJ_WS + row * 136 + cc) * 4,
                 W + (size_t)(k0 + row) * D_ + n0 + cc);
        }
    };

    stage(0, 0); CP_COMMIT();
    const int NIT = D_ / 32;                 // 16
    for (int kt = 0; kt < NIT; kt++) {
        int p = kt & 1;
        if (kt + 1 < NIT) { stage(kt + 1, p ^ 1); CP_COMMIT(); CP_WAIT(1); }
        else              { CP_WAIT(0); }
        __syncthreads();

        const float* Ab = Xs + p * PJ_XS;
        const float* Bb = Ws + p * PJ_WS;
#pragma unroll
        for (int ks = 0; ks < 2; ks++) {      // 2 x k16
            int k0 = ks * 16;
            uint32_t a[4][4], b[4][2];
#pragma unroll
            for (int mt = 0; mt < 4; mt++) {
                const float* pa = Ab + (warpM * 64 + mt * 16 + gid) * 36 + k0 + tg * 2;
                float2 f0 = *reinterpret_cast<const float2*>(pa);
                float2 f1 = *reinterpret_cast<const float2*>(pa + 8 * 36);
                float2 f2 = *reinterpret_cast<const float2*>(pa + 8);
                float2 f3 = *reinterpret_cast<const float2*>(pa + 8 * 36 + 8);
                a[mt][0] = f2h2(f0.x, f0.y);
                a[mt][1] = f2h2(f1.x, f1.y);
                a[mt][2] = f2h2(f2.x, f2.y);
                a[mt][3] = f2h2(f3.x, f3.y);
            }
#pragma unroll
            for (int nt = 0; nt < 4; nt++) {
                const float* pb = Bb + (k0 + tg * 2) * 136 + warpN * 32 + nt * 8 + gid;
                b[nt][0] = f2h2(pb[0], pb[136]);
                b[nt][1] = f2h2(pb[8 * 136], pb[9 * 136]);
            }
#pragma unroll
            for (int mt = 0; mt < 4; mt++)
#pragma unroll
                for (int nt = 0; nt < 4; nt++)
                    mma_f16(acc[mt][nt], a[mt], b[nt]);
        }
        __syncthreads();
    }

#pragma unroll
    for (int mt = 0; mt < 4; mt++) {
        int m = m0 + warpM * 64 + mt * 16 + gid;
        int bb = m >> 11;
        int l  = m & (L_ - 1);
#pragma unroll
        for (int nt = 0; nt < 4; nt++) {
            int n = n0 + warpN * 32 + nt * 8 + tg * 2;
            int h = n >> 6, e = n & 63;
            float2 bi = *reinterpret_cast<const float2*>(bias + n);
            float v0 = acc[mt][nt][0] + bi.x;
            float v1 = acc[mt][nt][1] + bi.y;
            float v2 = acc[mt][nt][2] + bi.x;
            float v3 = acc[mt][nt][3] + bi.y;
            if (z == 2) {
                __half* vt = g_vth + ((size_t)(bb * H_ + h)) * E_ * L_;
                vt[(size_t)e * L_ + l]           = __float2half(v0);
                vt[(size_t)(e + 1) * L_ + l]     = __float2half(v1);
                vt[(size_t)e * L_ + l + 8]       = __float2half(v2);
                vt[(size_t)(e + 1) * L_ + l + 8] = __float2half(v3);
            } else {
                __half* dst = z ? g_kh : g_qh;
                *reinterpret_cast<uint32_t*>(dst + (((size_t)(bb * H_ + h)) * L_ + l) * E_ + e) =
                    f2h2(v0, v1);
                *reinterpret_cast<uint32_t*>(dst + (((size_t)(bb * H_ + h)) * L_ + l + 8) * E_ + e) =
                    f2h2(v2, v3);
            }
        }
    }
}

// ---------------------------------------------------------------------------
// Kernel 2: scores + exp via fp16 m16n8k16 and ex2.approx.f16x2.
// Writes unnormalized exp to g_se fp16 (streaming), psums (fp32) to g_psum.
// CTA 128x128, full K=64 resident.  grid (16,16,32), 256 threads.
// ---------------------------------------------------------------------------
static constexpr int SQ = 72;
static constexpr int S_HB = 2 * 128 * SQ * 2;    // 36864 bytes
static constexpr int S_SMEM = S_HB + 512 * 4;    // 38912 B

__global__ void __launch_bounds__(256, 2) scores_mma()
{
    extern __shared__ char smc[];
    __half* Qs = reinterpret_cast<__half*>(smc);
    __half* Ks = Qs + 128 * SQ;
    float* red = reinterpret_cast<float*>(smc + S_HB);
    uint32_t sQ = smem_u32(Qs), sK = smem_u32(Ks);

    int t = threadIdx.x;
    int lane = t & 31, wid = t >> 5;
    int gid = lane >> 2, tg = lane & 3;
    int warpM = wid >> 2, warpN = wid & 3;
    int m0 = blockIdx.x * 128, n0 = blockIdx.y * 128, bh = blockIdx.z;

    const __half* Q = g_qh + (size_t)bh * L_ * E_;
    const __half* K = g_kh + (size_t)bh * L_ * E_;
    __half* Se = g_se + (size_t)bh * L_ * L_;

#pragma unroll
    for (int i = 0; i < 4; i++) {
        int idx = t + i * 256;
        int row = idx >> 3, g = idx & 7;
        cp16(sQ + (row * SQ + g * 8) * 2, Q + (size_t)(m0 + row) * E_ + g * 8);
        cp16(sK + (row * SQ + g * 8) * 2, K + (size_t)(n0 + row) * E_ + g * 8);
    }
    CP_COMMIT(); CP_WAIT(0);
    __syncthreads();

    float acc[4][4][4] = {};
#pragma unroll
    for (int ks = 0; ks < 4; ks++) {
        int k0 = ks * 16;
        uint32_t a[4][4], b[4][2];
#pragma unroll
        for (int mt = 0; mt < 4; mt++) {
            const __half* pa = Qs + (warpM * 64 + mt * 16 + gid) * SQ + k0 + tg * 2;
            a[mt][0] = *reinterpret_cast<const uint32_t*>(pa);
            a[mt][1] = *reinterpret_cast<const uint32_t*>(pa + 8 * SQ);
            a[mt][2] = *reinterpret_cast<const uint32_t*>(pa + 8);
            a[mt][3] = *reinterpret_cast<const uint32_t*>(pa + 8 * SQ + 8);
        }
#pragma unroll
        for (int nt = 0; nt < 4; nt++) {
            const __half* pb = Ks + (warpN * 32 + nt * 8 + gid) * SQ + k0 + tg * 2;
            b[nt][0] = *reinterpret_cast<const uint32_t*>(pb);
            b[nt][1] = *reinterpret_cast<const uint32_t*>(pb + 8);
        }
#pragma unroll
        for (int mt = 0; mt < 4; mt++)
#pragma unroll
            for (int nt = 0; nt < 4; nt++)
                mma_f16(acc[mt][nt], a[mt], b[nt]);
    }

    const float s2 = 0.125f * 1.4426950408889634f;
    float rowpart[4][2] = {};
#pragma unroll
    for (int mt = 0; mt < 4; mt++) {
        int r = m0 + warpM * 64 + mt * 16 + gid;
#pragma unroll
        for (int nt = 0; nt < 4; nt++) {
            int cc = n0 + warpN * 32 + nt * 8 + tg * 2;
            uint32_t e01 = ex2_h2(f2h2(acc[mt][nt][0] * s2, acc[mt][nt][1] * s2));
            uint32_t e23 = ex2_h2(f2h2(acc[mt][nt][2] * s2, acc[mt][nt][3] * s2));
            st_cs_h2(Se + (size_t)r * L_ + cc, e01);
            st_cs_h2(Se + (size_t)(r + 8) * L_ + cc, e23);
            float2 p01 = __half22float2(*reinterpret_cast<__half2*>(&e01));
            float2 p23 = __half22float2(*reinterpret_cast<__half2*>(&e23));
            rowpart[mt][0] += p01.x + p01.y;
            rowpart[mt][1] += p23.x + p23.y;
        }
    }

#pragma unroll
    for (int mt = 0; mt < 4; mt++) {
#pragma unroll
        for (int half = 0; half < 2; half++) {
            float v = rowpart[mt][half];
            v += __shfl_xor_sync(0xffffffffu, v, 1);
            v += __shfl_xor_sync(0xffffffffu, v, 2);
            if (tg == 0)
                red[warpN * 128 + warpM * 64 + mt * 16 + gid + half * 8] = v;
        }
    }
    __syncthreads();
    if (t < 128) {
        float s = red[t] + red[128 + t] + red[256 + t] + red[384 + t];
        g_psum[((size_t)bh * L_ + m0 + t) * 16 + blockIdx.y] = s;
    }
}

// ---------------------------------------------------------------------------
// Kernel 3: MERGED av + normalize via block specialization.
// Blocks [0, 512):    AV pipeline (fp16 MMA, out = attn_norm @ V), 3-stage
//                     cp.async, 46.6 KB SMEM, <=84 regs (3 CTAs/SM).
// Blocks [512, 66048): one attn row each: read fp16 exp, scale, write fp32.
// The heavy av blocks dispatch first; the DRAM-bound norm blocks stream into
// the remaining CTA slots and overlap av's latency-bound MMA phase.
// grid 66048 x 1D, 256 threads.
// ---------------------------------------------------------------------------
static constexpr int AV_A = 128 * 40;
static constexpr int AV_B = 64 * 40;
static constexpr int AV_HB = (3 * AV_A + 3 * AV_B) * 2;   // 46080 bytes
static constexpr int AV_SMEM = AV_HB + 128 * 4;           // 46592 B

__global__ void __launch_bounds__(256, 3) av_norm(float* __restrict__ attn,
                                                  float* __restrict__ out)
{
    int bx = blockIdx.x;
    int t = threadIdx.x;

    if (bx >= 512) {
        // ---------------- normalize path: one attn row ----------------
        int row = bx - 512;
        const __half* se = g_se + (size_t)row * L_;
        float* a = attn + (size_t)row * L_;

        const float* pp = g_psum + (size_t)row * 16;
        float s = 0.f;
#pragma unroll
        for (int j = 0; j < 16; j++) s += pp[j];
        float inv = 1.0f / s;

        uint4 hv = __ldcs(reinterpret_cast<const uint4*>(se + t * 8));
        float2 f0 = __half22float2(*reinterpret_cast<__half2*>(&hv.x));
        float2 f1 = __half22float2(*reinterpret_cast<__half2*>(&hv.y));
        float2 f2 = __half22float2(*reinterpret_cast<__half2*>(&hv.z));
        float2 f3 = __half22float2(*reinterpret_cast<__half2*>(&hv.w));
        st_cs4(a + t * 8,     make_float4(f0.x * inv, f0.y * inv, f1.x * inv, f1.y * inv));
        st_cs4(a + t * 8 + 4, make_float4(f2.x * inv, f2.y * inv, f3.x * inv, f3.y * inv));
        return;
    }

    // ---------------- AV path ----------------
    extern __shared__ char smc[];
    __half* As = reinterpret_cast<__half*>(smc);
    __half* Vs = As + 3 * AV_A;
    float* rowinv = reinterpret_cast<float*>(smc + AV_HB);
    uint32_t sA = smem_u32(As), sV = smem_u32(Vs);

    int lane = t & 31, wid = t >> 5;
    int gid = lane >> 2, tg = lane & 3;
    int warpM = wid >> 1, warpN = wid & 1;
    int bh = bx >> 4;
    int m0 = (bx & 15) * 128;
    int bb = bh >> 3, h = bh & 7;

    const __half* Se = g_se + (size_t)bh * L_ * L_;
    const __half* Vt = g_vth + (size_t)bh * E_ * L_;

    float acc[2][4][4] = {};

    auto stage = [&](int kt, int buf) {
        int k0 = kt * 32;
#pragma unroll
        for (int i = 0; i < 2; i++) {
            int idx = t + i * 256;
            int row = idx >> 2, g = idx & 3;
            cp16(sA + (buf * AV_A + row * 40 + g * 8) * 2,
                 Se + (size_t)(m0 + row) * L_ + k0 + g * 8);
        }
        {
            int row = t >> 2, g = t & 3;
            cp16(sV + (buf * AV_B + row * 40 + g * 8) * 2,
                 Vt + (size_t)row * L_ + k0 + g * 8);
        }
    };

    const int NIT = L_ / 32;                  // 64
    stage(0, 0); CP_COMMIT();
    stage(1, 1); CP_COMMIT();

    if (t < 128) {
        const float* pp = g_psum + ((size_t)bh * L_ + m0 + t) * 16;
        float s = 0.f;
#pragma unroll
        for (int j = 0; j < 16; j++) s += pp[j];
        rowinv[t] = 1.0f / s;
    }

    for (int kt = 0; kt < NIT; kt++) {
        __syncthreads();
        if (kt + 2 < NIT) { stage(kt + 2, (kt + 2) % 3); CP_COMMIT(); CP_WAIT(2); }
        else if (kt + 1 < NIT) { CP_WAIT(1); }
        else { CP_WAIT(0); }
        __syncthreads();

        int p = kt % 3;
        const __half* Ab = As + p * AV_A;
        const __half* Vb = Vs + p * AV_B;

#pragma unroll
        for (int ks = 0; ks < 2; ks++) {
            int kk = ks * 16;
            uint32_t a[2][4], b[4][2];
#pragma unroll
            for (int mt = 0; mt < 2; mt++) {
                int row = warpM * 32 + mt * 16 + gid;
                a[mt][0] = *reinterpret_cast<const uint32_t*>(Ab + row * 40 + kk + tg * 2);
                a[mt][1] = *reinterpret_cast<const uint32_t*>(Ab + (row + 8) * 40 + kk + tg * 2);
                a[mt][2] = *reinterpret_cast<const uint32_t*>(Ab + row * 40 + kk + tg * 2 + 8);
                a[mt][3] = *reinterpret_cast<const uint32_t*>(Ab + (row + 8) * 40 + kk + tg * 2 + 8);
            }
#pragma unroll
            for (int nt = 0; nt < 4; nt++) {
                int n = warpN * 32 + nt * 8 + gid;
                b[nt][0] = *reinterpret_cast<const uint32_t*>(Vb + n * 40 + kk + tg * 2);
                b[nt][1] = *reinterpret_cast<const uint32_t*>(Vb + n * 40 + kk + tg * 2 + 8);
            }
#pragma unroll
            for (int mt = 0; mt < 2; mt++)
#pragma unroll
                for (int nt = 0; nt < 4; nt++)
                    mma_f16(acc[mt][nt], a[mt], b[nt]);
        }
    }

#pragma unroll
    for (int mt = 0; mt < 2; mt++) {
        int rloc = warpM * 32 + mt * 16 + gid;
        int r = m0 + rloc;
        float s0 = rowinv[rloc], s1 = rowinv[rloc + 8];
#pragma unroll
        for (int nt = 0; nt < 4; nt++) {
            int cc = warpN * 32 + nt * 8 + tg * 2;
            *reinterpret_cast<float2*>(out + ((size_t)(bb * L_ + r)) * D_ + h * 64 + cc) =
                make_float2(acc[mt][nt][0] * s0, acc[mt][nt][1] * s0);
            *reinterpret_cast<float2*>(out + ((size_t)(bb * L_ + r + 8)) * D_ + h * 64 + cc) =
                make_float2(acc[mt][nt][2] * s1, acc[mt][nt][3] * s1);
        }
    }
}

// ---------------------------------------------------------------------------
extern "C" void kernel_launch(void* const* d_in, const int* in_sizes, int n_in,
                              void* d_out, int out_size)
{
    const float* queries = (const float*)d_in[0];
    const float* keys    = (const float*)d_in[1];
    const float* values  = (const float*)d_in[2];
    const float* Wq      = (const float*)d_in[3];
    const float* bq      = (const float*)d_in[4];
    const float* Wk      = (const float*)d_in[5];
    const float* bk      = (const float*)d_in[6];
    const float* Wv      = (const float*)d_in[7];
    const float* bv      = (const float*)d_in[8];

    float* out  = (float*)d_out;
    float* attn = out + (size_t)B_ * L_ * D_;   // tuple order: (out, attn)

    static bool attr_set = false;
    if (!attr_set) {
        cudaFuncSetAttribute(proj_all,   cudaFuncAttributeMaxDynamicSharedMemorySize, PJ_SMEM);
        cudaFuncSetAttribute(scores_mma, cudaFuncAttributeMaxDynamicSharedMemorySize, S_SMEM);
        cudaFuncSetAttribute(av_norm,    cudaFuncAttributeMaxDynamicSharedMemorySize, AV_SMEM);
        attr_set = true;
    }

    proj_all<<<dim3((B_ * L_) / 128, D_ / 128, 3), 256, PJ_SMEM>>>(
        queries, keys, values, Wq, Wk, Wv, bq, bk, bv);
    scores_mma<<<dim3(L_ / 128, L_ / 128, B_ * H_), 256, S_SMEM>>>();
    av_norm<<<dim3(512 + B_ * H_ * L_), 256, AV_SMEM>>>(attn, out);
}

// round 16
// speedup vs baseline: 1.2542x; 1.2542x over previous
#include <cuda_runtime.h>
#include <cuda_fp16.h>
#include <cstdint>

#define B_ 4
#define L_ 2048
#define D_ 512
#define H_ 8
#define E_ 64

// Projected Q/K fp16 [B,H,L,E]; V transposed fp16 [B,H,E,L].
__device__ __align__(256) __half g_qh[B_ * H_ * L_ * E_];
__device__ __align__(256) __half g_kh[B_ * H_ * L_ * E_];
__device__ __align__(256) __half g_vth[B_ * H_ * E_ * L_];
// Unnormalized exp(scores) scratch, fp16:
__device__ __align__(256) __half g_se[(size_t)B_ * H_ * L_ * L_];
// Per-row partial sums of exp(scores): [row_global][col_tile 0..15]
__device__ __align__(256) float g_psum[B_ * H_ * L_ * 16];

// ---------------------------------------------------------------------------
// helpers
// ---------------------------------------------------------------------------
__device__ __forceinline__ uint32_t smem_u32(const void* p) {
    uint32_t a;
    asm("{ .reg .u64 t; cvta.to.shared.u64 t, %1; cvt.u32.u64 %0, t; }"
        : "=r"(a) : "l"(p));
    return a;
}

__device__ __forceinline__ uint32_t rna(float x) {
    uint32_t r;
    asm("cvt.rna.tf32.f32 %0, %1;" : "=r"(r) : "f"(x));
    return r;
}

// pack two fp32 -> fp16x2 (lo, hi)
__device__ __forceinline__ uint32_t f2h2(float lo, float hi) {
    uint32_t r;
    asm("cvt.rn.f16x2.f32 %0, %1, %2;" : "=r"(r) : "f"(hi), "f"(lo));
    return r;
}

// 2^x on packed halfs
__device__ __forceinline__ uint32_t ex2_h2(uint32_t x) {
    uint32_t r;
    asm("ex2.approx.f16x2 %0, %1;" : "=r"(r) : "r"(x));
    return r;
}

// tf32 m16n8k8 (projection)
__device__ __forceinline__ void mma_tf32(float* d, const uint32_t* a, const uint32_t* b) {
    asm volatile(
        "mma.sync.aligned.m16n8k8.row.col.f32.tf32.tf32.f32 "
        "{%0,%1,%2,%3}, {%4,%5,%6,%7}, {%8,%9}, {%0,%1,%2,%3};"
        : "+f"(d[0]), "+f"(d[1]), "+f"(d[2]), "+f"(d[3])
        : "r"(a[0]), "r"(a[1]), "r"(a[2]), "r"(a[3]), "r"(b[0]), "r"(b[1]));
}

// fp16 m16n8k16, fp32 accum
__device__ __forceinline__ void mma_f16(float* d, const uint32_t* a, const uint32_t* b) {
    asm volatile(
        "mma.sync.aligned.m16n8k16.row.col.f32.f16.f16.f32 "
        "{%0,%1,%2,%3}, {%4,%5,%6,%7}, {%8,%9}, {%0,%1,%2,%3};"
        : "+f"(d[0]), "+f"(d[1]), "+f"(d[2]), "+f"(d[3])
        : "r"(a[0]), "r"(a[1]), "r"(a[2]), "r"(a[3]), "r"(b[0]), "r"(b[1]));
}

__device__ __forceinline__ void cp16(uint32_t dst, const void* src) {
    asm volatile("cp.async.cg.shared.global [%0], [%1], 16;"
                 :: "r"(dst), "l"(src) : "memory");
}
#define CP_COMMIT() asm volatile("cp.async.commit_group;" ::: "memory")
#define CP_WAIT(n)  asm volatile("cp.async.wait_group %0;" :: "n"(n) : "memory")

__device__ __forceinline__ void st_cs4(float* p, float4 v) {
    asm volatile("st.global.cs.v4.f32 [%0], {%1, %2, %3, %4};"
                 :: "l"(p), "f"(v.x), "f"(v.y), "f"(v.z), "f"(v.w) : "memory");
}
__device__ __forceinline__ void st_cs_h2(__half* p, uint32_t v) {
    asm volatile("st.global.cs.b32 [%0], %1;" :: "l"(p), "r"(v) : "memory");
}

// ---------------------------------------------------------------------------
// Kernel 1: QKV projection (1x tf32, RN-rounded operands) -- R12 proven form.
// z=0/1 -> Q/K fp16 [B,H,L,E];  z=2 -> V transposed fp16 [B,H,E,L].
// CTA 128x128, grid (64, 4, 3), 256 thr.
// ---------------------------------------------------------------------------
static constexpr int PJ_XS = 128 * 36;
static constexpr int PJ_WS = 32 * 136;
static constexpr int PJ_SMEM = (2 * PJ_XS + 2 * PJ_WS) * 4;   // 71680 B

__global__ void __launch_bounds__(256, 2) proj_mma(
    const float* __restrict__ X0, const float* __restrict__ X1,
    const float* __restrict__ X2,
    const float* __restrict__ W0, const float* __restrict__ W1,
    const float* __restrict__ W2,
    const float* __restrict__ b0, const float* __restrict__ b1,
    const float* __restrict__ b2)
{
    extern __shared__ float smf[];
    float* Xs = smf;
    float* Ws = smf + 2 * PJ_XS;
    uint32_t sX = smem_u32(Xs), sW = smem_u32(Ws);

    int z = blockIdx.z;
    const float* X = (z == 0) ? X0 : (z == 1) ? X1 : X2;
    const float* W = (z == 0) ? W0 : (z == 1) ? W1 : W2;
    const float* bias = (z == 0) ? b0 : (z == 1) ? b1 : b2;

    int t = threadIdx.x;
    int lane = t & 31, wid = t >> 5;
    int gid = lane >> 2, tg = lane & 3;
    int warpM = wid >> 2, warpN = wid & 3;
    int m0 = blockIdx.x * 128, n0 = blockIdx.y * 128;

    float acc[4][4][4] = {};

    auto stage = [&](int kt, int buf) {
        int k0 = kt * 32;
#pragma unroll
        for (int i = 0; i < 4; i++) {
            int idx = t + i * 256;
            int row = idx >> 3, cc = (idx & 7) * 4;
            cp16(sX + (buf * PJ_XS + row * 36 + cc) * 4,
                 X + (size_t)(m0 + row) * D_ + k0 + cc);
        }
#pragma unroll
        for (int i = 0; i < 4; i++) {
            int idx = t + i * 256;
            int row = idx >> 5, cc = (idx & 31) * 4;
            cp16(sW + (buf * PJ_WS + row * 136 + cc) * 4,
                 W + (size_t)(k0 + row) * D_ + n0 + cc);
        }
    };

    stage(0, 0); CP_COMMIT();
    const int NIT = D_ / 32;                 // 16
    for (int kt = 0; kt < NIT; kt++) {
        int p = kt & 1;
        if (kt + 1 < NIT) { stage(kt + 1, p ^ 1); CP_COMMIT(); CP_WAIT(1); }
        else              { CP_WAIT(0); }
        __syncthreads();

        const float* Ab = Xs + p * PJ_XS;
        const float* Bb = Ws + p * PJ_WS;
#pragma unroll
        for (int ks = 0; ks < 4; ks++) {
            int k0 = ks * 8;
            uint32_t a[4][4], b[4][2];
#pragma unroll
            for (int mt = 0; mt < 4; mt++) {
                const float* pa = Ab + (warpM * 64 + mt * 16 + gid) * 36 + k0 + tg;
                a[mt][0] = rna(pa[0]);
                a[mt][1] = rna(pa[8 * 36]);
                a[mt][2] = rna(pa[4]);
                a[mt][3] = rna(pa[8 * 36 + 4]);
            }
#pragma unroll
            for (int nt = 0; nt < 4; nt++) {
                const float* pb = Bb + (k0 + tg) * 136 + warpN * 32 + nt * 8 + gid;
                b[nt][0] = rna(pb[0]);
                b[nt][1] = rna(pb[4 * 136]);
            }
#pragma unroll
            for (int mt = 0; mt < 4; mt++)
#pragma unroll
                for (int nt = 0; nt < 4; nt++)
                    mma_tf32(acc[mt][nt], a[mt], b[nt]);
        }
        __syncthreads();
    }

#pragma unroll
    for (int mt = 0; mt < 4; mt++) {
        int m = m0 + warpM * 64 + mt * 16 + gid;
        int bb = m >> 11;
        int l  = m & (L_ - 1);
#pragma unroll
        for (int nt = 0; nt < 4; nt++) {
            int n = n0 + warpN * 32 + nt * 8 + tg * 2;
            int h = n >> 6, e = n & 63;
            float2 bi = *reinterpret_cast<const float2*>(bias + n);
            float v0 = acc[mt][nt][0] + bi.x;
            float v1 = acc[mt][nt][1] + bi.y;
            float v2 = acc[mt][nt][2] + bi.x;
            float v3 = acc[mt][nt][3] + bi.y;
            if (z == 2) {
                __half* vt = g_vth + ((size_t)(bb * H_ + h)) * E_ * L_;
                vt[(size_t)e * L_ + l]           = __float2half(v0);
                vt[(size_t)(e + 1) * L_ + l]     = __float2half(v1);
                vt[(size_t)e * L_ + l + 8]       = __float2half(v2);
                vt[(size_t)(e + 1) * L_ + l + 8] = __float2half(v3);
            } else {
                __half* dst = z ? g_kh : g_qh;
                *reinterpret_cast<uint32_t*>(dst + (((size_t)(bb * H_ + h)) * L_ + l) * E_ + e) =
                    f2h2(v0, v1);
                *reinterpret_cast<uint32_t*>(dst + (((size_t)(bb * H_ + h)) * L_ + l + 8) * E_ + e) =
                    f2h2(v2, v3);
            }
        }
    }
}

// ---------------------------------------------------------------------------
// Kernel 2: scores + exp via fp16 m16n8k16 and ex2.approx.f16x2 (R13 form).
// CTA 128x128, full K=64 resident.  grid (16,16,32), 256 threads.
// ---------------------------------------------------------------------------
static constexpr int SQ = 72;
static constexpr int S_HB = 2 * 128 * SQ * 2;    // 36864 bytes
static constexpr int S_SMEM = S_HB + 512 * 4;    // 38912 B

__global__ void __launch_bounds__(256, 2) scores_mma()
{
    extern __shared__ char smc[];
    __half* Qs = reinterpret_cast<__half*>(smc);
    __half* Ks = Qs + 128 * SQ;
    float* red = reinterpret_cast<float*>(smc + S_HB);
    uint32_t sQ = smem_u32(Qs), sK = smem_u32(Ks);

    int t = threadIdx.x;
    int lane = t & 31, wid = t >> 5;
    int gid = lane >> 2, tg = lane & 3;
    int warpM = wid >> 2, warpN = wid & 3;
    int m0 = blockIdx.x * 128, n0 = blockIdx.y * 128, bh = blockIdx.z;

    const __half* Q = g_qh + (size_t)bh * L_ * E_;
    const __half* K = g_kh + (size_t)bh * L_ * E_;
    __half* Se = g_se + (size_t)bh * L_ * L_;

#pragma unroll
    for (int i = 0; i < 4; i++) {
        int idx = t + i * 256;
        int row = idx >> 3, g = idx & 7;
        cp16(sQ + (row * SQ + g * 8) * 2, Q + (size_t)(m0 + row) * E_ + g * 8);
        cp16(sK + (row * SQ + g * 8) * 2, K + (size_t)(n0 + row) * E_ + g * 8);
    }
    CP_COMMIT(); CP_WAIT(0);
    __syncthreads();

    float acc[4][4][4] = {};
#pragma unroll
    for (int ks = 0; ks < 4; ks++) {
        int k0 = ks * 16;
        uint32_t a[4][4], b[4][2];
#pragma unroll
        for (int mt = 0; mt < 4; mt++) {
            const __half* pa = Qs + (warpM * 64 + mt * 16 + gid) * SQ + k0 + tg * 2;
            a[mt][0] = *reinterpret_cast<const uint32_t*>(pa);
            a[mt][1] = *reinterpret_cast<const uint32_t*>(pa + 8 * SQ);
            a[mt][2] = *reinterpret_cast<const uint32_t*>(pa + 8);
            a[mt][3] = *reinterpret_cast<const uint32_t*>(pa + 8 * SQ + 8);
        }
#pragma unroll
        for (int nt = 0; nt < 4; nt++) {
            const __half* pb = Ks + (warpN * 32 + nt * 8 + gid) * SQ + k0 + tg * 2;
            b[nt][0] = *reinterpret_cast<const uint32_t*>(pb);
            b[nt][1] = *reinterpret_cast<const uint32_t*>(pb + 8);
        }
#pragma unroll
        for (int mt = 0; mt < 4; mt++)
#pragma unroll
            for (int nt = 0; nt < 4; nt++)
                mma_f16(acc[mt][nt], a[mt], b[nt]);
    }

    const float s2 = 0.125f * 1.4426950408889634f;
    float rowpart[4][2] = {};
#pragma unroll
    for (int mt = 0; mt < 4; mt++) {
        int r = m0 + warpM * 64 + mt * 16 + gid;
#pragma unroll
        for (int nt = 0; nt < 4; nt++) {
            int cc = n0 + warpN * 32 + nt * 8 + tg * 2;
            uint32_t e01 = ex2_h2(f2h2(acc[mt][nt][0] * s2, acc[mt][nt][1] * s2));
            uint32_t e23 = ex2_h2(f2h2(acc[mt][nt][2] * s2, acc[mt][nt][3] * s2));
            st_cs_h2(Se + (size_t)r * L_ + cc, e01);
            st_cs_h2(Se + (size_t)(r + 8) * L_ + cc, e23);
            float2 p01 = __half22float2(*reinterpret_cast<__half2*>(&e01));
            float2 p23 = __half22float2(*reinterpret_cast<__half2*>(&e23));
            rowpart[mt][0] += p01.x + p01.y;
            rowpart[mt][1] += p23.x + p23.y;
        }
    }

#pragma unroll
    for (int mt = 0; mt < 4; mt++) {
#pragma unroll
        for (int half = 0; half < 2; half++) {
            float v = rowpart[mt][half];
            v += __shfl_xor_sync(0xffffffffu, v, 1);
            v += __shfl_xor_sync(0xffffffffu, v, 2);
            if (tg == 0)
                red[warpN * 128 + warpM * 64 + mt * 16 + gid + half * 8] = v;
        }
    }
    __syncthreads();
    if (t < 128) {
        float s = red[t] + red[128 + t] + red[256 + t] + red[384 + t];
        g_psum[((size_t)bh * L_ + m0 + t) * 16 + blockIdx.y] = s;
    }
}

// ---------------------------------------------------------------------------
// Kernel 3: AV + normalize write-back, 64-row stripes for occupancy.
// CTA 64x64 out tile, 3-stage cp.async, fused fp32 attn writeback.
// grid (32, 1, 32) = 1024 CTAs, 256 threads, 3 CTAs/SM target.
// SMEM: As[3][64][40]h | Vs[3][64][40]h | rowinv[64] f32 = 30976 B
// ---------------------------------------------------------------------------
static constexpr int AV_A = 64 * 40;
static constexpr int AV_B = 64 * 40;
static constexpr int AV_HB = (3 * AV_A + 3 * AV_B) * 2;   // 30720 bytes
static constexpr int AV_SMEM = AV_HB + 64 * 4;            // 30976 B

__global__ void __launch_bounds__(256, 3) av_mma(float* __restrict__ attn,
                                                 float* __restrict__ out)
{
    extern __shared__ char smc[];
    __half* As = reinterpret_cast<__half*>(smc);
    __half* Vs = As + 3 * AV_A;
    float* rowinv = reinterpret_cast<float*>(smc + AV_HB);
    uint32_t sA = smem_u32(As), sV = smem_u32(Vs);

    int t = threadIdx.x;
    int lane = t & 31, wid = t >> 5;
    int gid = lane >> 2, tg = lane & 3;
    int warpM = wid >> 1, warpN = wid & 1;   // 4M x 2N over 64x64
    int m0 = blockIdx.x * 64, bh = blockIdx.z;
    int bb = bh >> 3, h = bh & 7;

    const __half* Se = g_se + (size_t)bh * L_ * L_;
    const __half* Vt = g_vth + (size_t)bh * E_ * L_;
    float* A = attn + (size_t)bh * L_ * L_;

    float acc[4][4] = {};

    auto stage = [&](int kt, int buf) {
        int k0 = kt * 32;
        {   // A: 64 rows x 32 halfs = 256 cp16
            int row = t >> 2, g = t & 3;
            cp16(sA + (buf * AV_A + row * 40 + g * 8) * 2,
                 Se + (size_t)(m0 + row) * L_ + k0 + g * 8);
        }
        {   // V^T: 64 rows x 32 halfs = 256 cp16
            int row = t >> 2, g = t & 3;
            cp16(sV + (buf * AV_B + row * 40 + g * 8) * 2,
                 Vt + (size_t)row * L_ + k0 + g * 8);
        }
    };

    const int NIT = L_ / 32;                  // 64
    stage(0, 0); CP_COMMIT();
    stage(1, 1); CP_COMMIT();

    if (t < 64) {
        const float* pp = g_psum + ((size_t)bh * L_ + m0 + t) * 16;
        float s = 0.f;
#pragma unroll
        for (int j = 0; j < 16; j++) s += pp[j];
        rowinv[t] = 1.0f / s;
    }

    for (int kt = 0; kt < NIT; kt++) {
        __syncthreads();
        if (kt + 2 < NIT) { stage(kt + 2, (kt + 2) % 3); CP_COMMIT(); CP_WAIT(2); }
        else if (kt + 1 < NIT) { CP_WAIT(1); }
        else { CP_WAIT(0); }
        __syncthreads();

        int p = kt % 3;
        const __half* Ab = As + p * AV_A;
        const __half* Vb = Vs + p * AV_B;

        // normalized fp32 write-back of this attn tile (64 x 32)
        {
            int k0 = kt * 32;
            int row = t >> 2, g = t & 3;
            uint4 hv = *reinterpret_cast<const uint4*>(Ab + row * 40 + g * 8);
            float s = rowinv[row];
            float2 f0 = __half22float2(*reinterpret_cast<__half2*>(&hv.x));
            float2 f1 = __half22float2(*reinterpret_cast<__half2*>(&hv.y));
            float2 f2 = __half22float2(*reinterpret_cast<__half2*>(&hv.z));
            float2 f3 = __half22float2(*reinterpret_cast<__half2*>(&hv.w));
            st_cs4(A + (size_t)(m0 + row) * L_ + k0 + g * 8,
                   make_float4(f0.x * s, f0.y * s, f1.x * s, f1.y * s));
            st_cs4(A + (size_t)(m0 + row) * L_ + k0 + g * 8 + 4,
                   make_float4(f2.x * s, f2.y * s, f3.x * s, f3.y * s));
        }

#pragma unroll
        for (int ks = 0; ks < 2; ks++) {
            int kk = ks * 16;
            uint32_t a[4], b[4][2];
            {
                int row = warpM * 16 + gid;
                a[0] = *reinterpret_cast<const uint32_t*>(Ab + row * 40 + kk + tg * 2);
                a[1] = *reinterpret_cast<const uint32_t*>(Ab + (row + 8) * 40 + kk + tg * 2);
                a[2] = *reinterpret_cast<const uint32_t*>(Ab + row * 40 + kk + tg * 2 + 8);
                a[3] = *reinterpret_cast<const uint32_t*>(Ab + (row + 8) * 40 + kk + tg * 2 + 8);
            }
#pragma unroll
            for (int nt = 0; nt < 4; nt++) {
                int n = warpN * 32 + nt * 8 + gid;
                b[nt][0] = *reinterpret_cast<const uint32_t*>(Vb + n * 40 + kk + tg * 2);
                b[nt][1] = *reinterpret_cast<const uint32_t*>(Vb + n * 40 + kk + tg * 2 + 8);
            }
#pragma unroll
            for (int nt = 0; nt < 4; nt++)
                mma_f16(acc[nt], a, b[nt]);
        }
    }

    {
        int rloc = warpM * 16 + gid;
        int r = m0 + rloc;
        float s0 = rowinv[rloc], s1 = rowinv[rloc + 8];
#pragma unroll
        for (int nt = 0; nt < 4; nt++) {
            int cc = warpN * 32 + nt * 8 + tg * 2;
            *reinterpret_cast<float2*>(out + ((size_t)(bb * L_ + r)) * D_ + h * 64 + cc) =
                make_float2(acc[nt][0] * s0, acc[nt][1] * s0);
            *reinterpret_cast<float2*>(out + ((size_t)(bb * L_ + r + 8)) * D_ + h * 64 + cc) =
                make_float2(acc[nt][2] * s1, acc[nt][3] * s1);
        }
    }
}

// ---------------------------------------------------------------------------
extern "C" void kernel_launch(void* const* d_in, const int* in_sizes, int n_in,
                              void* d_out, int out_size)
{
    const float* queries = (const float*)d_in[0];
    const float* keys    = (const float*)d_in[1];
    const float* values  = (const float*)d_in[2];
    const float* Wq      = (const float*)d_in[3];
    const float* bq      = (const float*)d_in[4];
    const float* Wk      = (const float*)d_in[5];
    const float* bk      = (const float*)d_in[6];
    const float* Wv      = (const float*)d_in[7];
    const float* bv      = (const float*)d_in[8];

    float* out  = (float*)d_out;
    float* attn = out + (size_t)B_ * L_ * D_;   // tuple order: (out, attn)

    static bool attr_set = false;
    if (!attr_set) {
        cudaFuncSetAttribute(proj_mma,   cudaFuncAttributeMaxDynamicSharedMemorySize, PJ_SMEM);
        cudaFuncSetAttribute(scores_mma, cudaFuncAttributeMaxDynamicSharedMemorySize, S_SMEM);
        cudaFuncSetAttribute(av_mma,     cudaFuncAttributeMaxDynamicSharedMemorySize, AV_SMEM);
        attr_set = true;
    }

    proj_mma<<<dim3((B_ * L_) / 128, D_ / 128, 3), 256, PJ_SMEM>>>(
        queries, keys, values, Wq, Wk, Wv, bq, bk, bv);
    scores_mma<<<dim3(L_ / 128, L_ / 128, B_ * H_), 256, S_SMEM>>>();
    av_mma<<<dim3(L_ / 64, 1, B_ * H_), 256, AV_SMEM>>>(attn, out);
}

// round 17
// speedup vs baseline: 1.3508x; 1.0770x over previous
#include <cuda_runtime.h>
#include <cuda_fp16.h>
#include <cstdint>

#define B_ 4
#define L_ 2048
#define D_ 512
#define H_ 8
#define E_ 64

// fp16 copies of inputs for the Q/K projection
__device__ __align__(256) __half g_xq[B_ * L_ * D_];
__device__ __align__(256) __half g_xk[B_ * L_ * D_];
__device__ __align__(256) __half g_wqt[D_ * D_];   // Wq^T [n][k]
__device__ __align__(256) __half g_wkt[D_ * D_];   // Wk^T [n][k]
// Projected Q/K fp16 [B,H,L,E]; V transposed fp16 [B,H,E,L].
__device__ __align__(256) __half g_qh[B_ * H_ * L_ * E_];
__device__ __align__(256) __half g_kh[B_ * H_ * L_ * E_];
__device__ __align__(256) __half g_vth[B_ * H_ * E_ * L_];
// Unnormalized exp(scores) scratch, fp16:
__device__ __align__(256) __half g_se[(size_t)B_ * H_ * L_ * L_];
// Per-row partial sums of exp(scores): [row_global][col_tile 0..15]
__device__ __align__(256) float g_psum[B_ * H_ * L_ * 16];

// ---------------------------------------------------------------------------
// helpers
// ---------------------------------------------------------------------------
__device__ __forceinline__ uint32_t smem_u32(const void* p) {
    uint32_t a;
    asm("{ .reg .u64 t; cvta.to.shared.u64 t, %1; cvt.u32.u64 %0, t; }"
        : "=r"(a) : "l"(p));
    return a;
}

__device__ __forceinline__ uint32_t rna(float x) {
    uint32_t r;
    asm("cvt.rna.tf32.f32 %0, %1;" : "=r"(r) : "f"(x));
    return r;
}

__device__ __forceinline__ uint32_t f2h2(float lo, float hi) {
    uint32_t r;
    asm("cvt.rn.f16x2.f32 %0, %1, %2;" : "=r"(r) : "f"(hi), "f"(lo));
    return r;
}

__device__ __forceinline__ uint32_t ex2_h2(uint32_t x) {
    uint32_t r;
    asm("ex2.approx.f16x2 %0, %1;" : "=r"(r) : "r"(x));
    return r;
}

__device__ __forceinline__ void mma_tf32(float* d, const uint32_t* a, const uint32_t* b) {
    asm volatile(
        "mma.sync.aligned.m16n8k8.row.col.f32.tf32.tf32.f32 "
        "{%0,%1,%2,%3}, {%4,%5,%6,%7}, {%8,%9}, {%0,%1,%2,%3};"
        : "+f"(d[0]), "+f"(d[1]), "+f"(d[2]), "+f"(d[3])
        : "r"(a[0]), "r"(a[1]), "r"(a[2]), "r"(a[3]), "r"(b[0]), "r"(b[1]));
}

__device__ __forceinline__ void mma_f16(float* d, const uint32_t* a, const uint32_t* b) {
    asm volatile(
        "mma.sync.aligned.m16n8k16.row.col.f32.f16.f16.f32 "
        "{%0,%1,%2,%3}, {%4,%5,%6,%7}, {%8,%9}, {%0,%1,%2,%3};"
        : "+f"(d[0]), "+f"(d[1]), "+f"(d[2]), "+f"(d[3])
        : "r"(a[0]), "r"(a[1]), "r"(a[2]), "r"(a[3]), "r"(b[0]), "r"(b[1]));
}

__device__ __forceinline__ void cp16(uint32_t dst, const void* src) {
    asm volatile("cp.async.cg.shared.global [%0], [%1], 16;"
                 :: "r"(dst), "l"(src) : "memory");
}
#define CP_COMMIT() asm volatile("cp.async.commit_group;" ::: "memory")
#define CP_WAIT(n)  asm volatile("cp.async.wait_group %0;" :: "n"(n) : "memory")

__device__ __forceinline__ void st_cs4(float* p, float4 v) {
    asm volatile("st.global.cs.v4.f32 [%0], {%1, %2, %3, %4};"
                 :: "l"(p), "f"(v.x), "f"(v.y), "f"(v.z), "f"(v.w) : "memory");
}
__device__ __forceinline__ void st_cs_u4(void* p, uint4 v) {
    asm volatile("st.global.cs.v4.b32 [%0], {%1, %2, %3, %4};"
                 :: "l"(p), "r"(v.x), "r"(v.y), "r"(v.z), "r"(v.w) : "memory");
}

// ---------------------------------------------------------------------------
// Kernel 0a: convert queries/keys fp32 -> fp16.  grid (4096, 2), 256 thr.
// ---------------------------------------------------------------------------
__global__ void cvt_x(const float* __restrict__ X0, const float* __restrict__ X1)
{
    const float* X = blockIdx.y ? X1 : X0;
    __half* Xh = blockIdx.y ? g_xk : g_xq;
    int i = blockIdx.x * 256 + threadIdx.x;        // float4 index
    float4 v = reinterpret_cast<const float4*>(X)[i];
    uint2 h;
    h.x = f2h2(v.x, v.y);
    h.y = f2h2(v.z, v.w);
    reinterpret_cast<uint2*>(Xh)[i] = h;
}

// ---------------------------------------------------------------------------
// Kernel 0b: transpose+convert Wq/Wk -> fp16 [n][k].  grid (16,16,2), 256 thr.
// ---------------------------------------------------------------------------
__global__ void cvt_wt(const float* __restrict__ W0, const float* __restrict__ W1)
{
    __shared__ float tile[32][33];
    const float* W = blockIdx.z ? W1 : W0;
    __half* Wt = blockIdx.z ? g_wkt : g_wqt;

    int tx = threadIdx.x & 31, ty = threadIdx.x >> 5;   // 32 x 8
    int n = blockIdx.x * 32 + tx;
    int k0 = blockIdx.y * 32;
#pragma unroll
    for (int i = 0; i < 32; i += 8)
        tile[ty + i][tx] = W[(size_t)(k0 + ty + i) * D_ + n];
    __syncthreads();
#pragma unroll
    for (int i = 0; i < 32; i += 8)
        Wt[(size_t)(blockIdx.x * 32 + ty + i) * D_ + k0 + tx] =
            __float2half(tile[tx][ty + i]);
}

// ---------------------------------------------------------------------------
// Kernel 1a: Q/K projection, pure fp16 MMA pipeline.
// A = Xh [m][k] fp16, B = Wt [n][k] fp16.  CTA 128x128, K=512 in BK=64,
// double buffer.  grid (64, 4, 2), 256 thr.
// SMEM: Xs[2][128][72]h | Ws[2][128][72]h = 73728 B
// ---------------------------------------------------------------------------
static constexpr int PQ = 72;
static constexpr int PQ_BUF = 128 * PQ;          // halfs
static constexpr int PQK_SMEM = 4 * PQ_BUF * 2;  // 73728 B

__global__ void __launch_bounds__(256, 2) proj_qk16(
    const float* __restrict__ b0, const float* __restrict__ b1)
{
    extern __shared__ char smc[];
    __half* Xs = reinterpret_cast<__half*>(smc);
    __half* Ws = Xs + 2 * PQ_BUF;
    uint32_t sX = smem_u32(Xs), sW = smem_u32(Ws);

    int z = blockIdx.z;
    const __half* X = z ? g_xk : g_xq;
    const __half* Wt = z ? g_wkt : g_wqt;
    const float* bias = z ? b1 : b0;
    __half* dst = z ? g_kh : g_qh;

    int t = threadIdx.x;
    int lane = t & 31, wid = t >> 5;
    int gid = lane >> 2, tg = lane & 3;
    int warpM = wid >> 2, warpN = wid & 3;
    int m0 = blockIdx.x * 128, n0 = blockIdx.y * 128;

    float acc[4][4][4] = {};

    auto stage = [&](int kt, int buf) {
        int k0 = kt * 64;
        // 128 rows x 64 halfs = 8 cp16/row, 1024 total -> 4 iters
#pragma unroll
        for (int i = 0; i < 4; i++) {
            int idx = t + i * 256;
            int row = idx >> 3, g = idx & 7;
            cp16(sX + (buf * PQ_BUF + row * PQ + g * 8) * 2,
                 X + (size_t)(m0 + row) * D_ + k0 + g * 8);
            cp16(sW + (buf * PQ_BUF + row * PQ + g * 8) * 2,
                 Wt + (size_t)(n0 + row) * D_ + k0 + g * 8);
        }
    };

    stage(0, 0); CP_COMMIT();
    const int NIT = D_ / 64;                 // 8
    for (int kt = 0; kt < NIT; kt++) {
        int p = kt & 1;
        if (kt + 1 < NIT) { stage(kt + 1, p ^ 1); CP_COMMIT(); CP_WAIT(1); }
        else              { CP_WAIT(0); }
        __syncthreads();

        const __half* Ab = Xs + p * PQ_BUF;
        const __half* Bb = Ws + p * PQ_BUF;
#pragma unroll
        for (int ks = 0; ks < 4; ks++) {
            int k0 = ks * 16;
            uint32_t a[4][4], b[4][2];
#pragma unroll
            for (int mt = 0; mt < 4; mt++) {
                const __half* pa = Ab + (warpM * 64 + mt * 16 + gid) * PQ + k0 + tg * 2;
                a[mt][0] = *reinterpret_cast<const uint32_t*>(pa);
                a[mt][1] = *reinterpret_cast<const uint32_t*>(pa + 8 * PQ);
                a[mt][2] = *reinterpret_cast<const uint32_t*>(pa + 8);
                a[mt][3] = *reinterpret_cast<const uint32_t*>(pa + 8 * PQ + 8);
            }
#pragma unroll
            for (int nt = 0; nt < 4; nt++) {
                const __half* pb = Bb + (warpN * 32 + nt * 8 + gid) * PQ + k0 + tg * 2;
                b[nt][0] = *reinterpret_cast<const uint32_t*>(pb);
                b[nt][1] = *reinterpret_cast<const uint32_t*>(pb + 8);
            }
#pragma unroll
            for (int mt = 0; mt < 4; mt++)
#pragma unroll
                for (int nt = 0; nt < 4; nt++)
                    mma_f16(acc[mt][nt], a[mt], b[nt]);
        }
        __syncthreads();
    }

#pragma unroll
    for (int mt = 0; mt < 4; mt++) {
        int m = m0 + warpM * 64 + mt * 16 + gid;
        int bb = m >> 11;
        int l  = m & (L_ - 1);
#pragma unroll
        for (int nt = 0; nt < 4; nt++) {
            int n = n0 + warpN * 32 + nt * 8 + tg * 2;
            int h = n >> 6, e = n & 63;
            float2 bi = *reinterpret_cast<const float2*>(bias + n);
            *reinterpret_cast<uint32_t*>(dst + (((size_t)(bb * H_ + h)) * L_ + l) * E_ + e) =
                f2h2(acc[mt][nt][0] + bi.x, acc[mt][nt][1] + bi.y);
            *reinterpret_cast<uint32_t*>(dst + (((size_t)(bb * H_ + h)) * L_ + l + 8) * E_ + e) =
                f2h2(acc[mt][nt][2] + bi.x, acc[mt][nt][3] + bi.y);
        }
    }
}

// ---------------------------------------------------------------------------
// Kernel 1b: V projection (1x tf32, RN-rounded) -> transposed fp16 [B,H,E,L].
// CTA 128x128, grid (64, 4), 256 thr.
// ---------------------------------------------------------------------------
static constexpr int PJ_XS = 128 * 36;
static constexpr int PJ_WS = 32 * 136;
static constexpr int PJ_SMEM = (2 * PJ_XS + 2 * PJ_WS) * 4;   // 71680 B

__global__ void __launch_bounds__(256, 2) proj_v(
    const float* __restrict__ X, const float* __restrict__ W,
    const float* __restrict__ bias)
{
    extern __shared__ float smf[];
    float* Xs = smf;
    float* Ws = smf + 2 * PJ_XS;
    uint32_t sX = smem_u32(Xs), sW = smem_u32(Ws);

    int t = threadIdx.x;
    int lane = t & 31, wid = t >> 5;
    int gid = lane >> 2, tg = lane & 3;
    int warpM = wid >> 2, warpN = wid & 3;
    int m0 = blockIdx.x * 128, n0 = blockIdx.y * 128;

    float acc[4][4][4] = {};

    auto stage = [&](int kt, int buf) {
        int k0 = kt * 32;
#pragma unroll
        for (int i = 0; i < 4; i++) {
            int idx = t + i * 256;
            int row = idx >> 3, cc = (idx & 7) * 4;
            cp16(sX + (buf * PJ_XS + row * 36 + cc) * 4,
                 X + (size_t)(m0 + row) * D_ + k0 + cc);
        }
#pragma unroll
        for (int i = 0; i < 4; i++) {
            int idx = t + i * 256;
            int row = idx >> 5, cc = (idx & 31) * 4;
            cp16(sW + (buf * PJ_WS + row * 136 + cc) * 4,
                 W + (size_t)(k0 + row) * D_ + n0 + cc);
        }
    };

    stage(0, 0); CP_COMMIT();
    const int NIT = D_ / 32;
    for (int kt = 0; kt < NIT; kt++) {
        int p = kt & 1;
        if (kt + 1 < NIT) { stage(kt + 1, p ^ 1); CP_COMMIT(); CP_WAIT(1); }
        else              { CP_WAIT(0); }
        __syncthreads();

        const float* Ab = Xs + p * PJ_XS;
        const float* Bb = Ws + p * PJ_WS;
#pragma unroll
        for (int ks = 0; ks < 4; ks++) {
            int k0 = ks * 8;
            uint32_t a[4][4], b[4][2];
#pragma unroll
            for (int mt = 0; mt < 4; mt++) {
                const float* pa = Ab + (warpM * 64 + mt * 16 + gid) * 36 + k0 + tg;
                a[mt][0] = rna(pa[0]);
                a[mt][1] = rna(pa[8 * 36]);
                a[mt][2] = rna(pa[4]);
                a[mt][3] = rna(pa[8 * 36 + 4]);
            }
#pragma unroll
            for (int nt = 0; nt < 4; nt++) {
                const float* pb = Bb + (k0 + tg) * 136 + warpN * 32 + nt * 8 + gid;
                b[nt][0] = rna(pb[0]);
                b[nt][1] = rna(pb[4 * 136]);
            }
#pragma unroll
            for (int mt = 0; mt < 4; mt++)
#pragma unroll
                for (int nt = 0; nt < 4; nt++)
                    mma_tf32(acc[mt][nt], a[mt], b[nt]);
        }
        __syncthreads();
    }

#pragma unroll
    for (int mt = 0; mt < 4; mt++) {
        int m = m0 + warpM * 64 + mt * 16 + gid;
        int bb = m >> 11;
        int l  = m & (L_ - 1);
#pragma unroll
        for (int nt = 0; nt < 4; nt++) {
            int n = n0 + warpN * 32 + nt * 8 + tg * 2;
            int h = n >> 6, e = n & 63;
            float2 bi = *reinterpret_cast<const float2*>(bias + n);
            __half* vt = g_vth + ((size_t)(bb * H_ + h)) * E_ * L_;
            vt[(size_t)e * L_ + l]           = __float2half(acc[mt][nt][0] + bi.x);
            vt[(size_t)(e + 1) * L_ + l]     = __float2half(acc[mt][nt][1] + bi.y);
            vt[(size_t)e * L_ + l + 8]       = __float2half(acc[mt][nt][2] + bi.x);
            vt[(size_t)(e + 1) * L_ + l + 8] = __float2half(acc[mt][nt][3] + bi.y);
        }
    }
}

// ---------------------------------------------------------------------------
// Kernel 2: scores + exp via fp16 MMA + ex2, SMEM-staged coalesced stores.
// CTA 128x128, full K=64 resident.  grid (16,16,32), 256 threads.
// SMEM: Qs/Ks [128][72]h (36864 B, reused as Ss[128][136]h = 34816 B)
//       red[512] f32.  Total 38912 B.
// ---------------------------------------------------------------------------
static constexpr int SQ = 72;
static constexpr int S_HB = 2 * 128 * SQ * 2;    // 36864 bytes
static constexpr int S_SMEM = S_HB + 512 * 4;    // 38912 B

__global__ void __launch_bounds__(256, 2) scores_mma()
{
    extern __shared__ char smc[];
    __half* Qs = reinterpret_cast<__half*>(smc);
    __half* Ks = Qs + 128 * SQ;
    float* red = reinterpret_cast<float*>(smc + S_HB);
    uint32_t sQ = smem_u32(Qs), sK = smem_u32(Ks);

    int t = threadIdx.x;
    int lane = t & 31, wid = t >> 5;
    int gid = lane >> 2, tg = lane & 3;
    int warpM = wid >> 2, warpN = wid & 3;
    int m0 = blockIdx.x * 128, n0 = blockIdx.y * 128, bh = blockIdx.z;

    const __half* Q = g_qh + (size_t)bh * L_ * E_;
    const __half* K = g_kh + (size_t)bh * L_ * E_;
    __half* Se = g_se + (size_t)bh * L_ * L_;

#pragma unroll
    for (int i = 0; i < 4; i++) {
        int idx = t + i * 256;
        int row = idx >> 3, g = idx & 7;
        cp16(sQ + (row * SQ + g * 8) * 2, Q + (size_t)(m0 + row) * E_ + g * 8);
        cp16(sK + (row * SQ + g * 8) * 2, K + (size_t)(n0 + row) * E_ + g * 8);
    }
    CP_COMMIT(); CP_WAIT(0);
    __syncthreads();

    float acc[4][4][4] = {};
#pragma unroll
    for (int ks = 0; ks < 4; ks++) {
        int k0 = ks * 16;
        uint32_t a[4][4], b[4][2];
#pragma unroll
        for (int mt = 0; mt < 4; mt++) {
            const __half* pa = Qs + (warpM * 64 + mt * 16 + gid) * SQ + k0 + tg * 2;
            a[mt][0] = *reinterpret_cast<const uint32_t*>(pa);
            a[mt][1] = *reinterpret_cast<const uint32_t*>(pa + 8 * SQ);
            a[mt][2] = *reinterpret_cast<const uint32_t*>(pa + 8);
            a[mt][3] = *reinterpret_cast<const uint32_t*>(pa + 8 * SQ + 8);
        }
#pragma unroll
        for (int nt = 0; nt < 4; nt++) {
            const __half* pb = Ks + (warpN * 32 + nt * 8 + gid) * SQ + k0 + tg * 2;
            b[nt][0] = *reinterpret_cast<const uint32_t*>(pb);
            b[nt][1] = *reinterpret_cast<const uint32_t*>(pb + 8);
        }
#pragma unroll
        for (int mt = 0; mt < 4; mt++)
#pragma unroll
            for (int nt = 0; nt < 4; nt++)
                mma_f16(acc[mt][nt], a[mt], b[nt]);
    }

    __syncthreads();                          // all Qs/Ks reads done
    __half* Ss = Qs;                          // reuse as [128][136]

    const float s2 = 0.125f * 1.4426950408889634f;
    float rowpart[4][2] = {};
#pragma unroll
    for (int mt = 0; mt < 4; mt++) {
        int rl = warpM * 64 + mt * 16 + gid;
#pragma unroll
        for (int nt = 0; nt < 4; nt++) {
            int cl = warpN * 32 + nt * 8 + tg * 2;
            uint32_t e01 = ex2_h2(f2h2(acc[mt][nt][0] * s2, acc[mt][nt][1] * s2));
            uint32_t e23 = ex2_h2(f2h2(acc[mt][nt][2] * s2, acc[mt][nt][3] * s2));
            *reinterpret_cast<uint32_t*>(Ss + rl * 136 + cl) = e01;
            *reinterpret_cast<uint32_t*>(Ss + (rl + 8) * 136 + cl) = e23;
            float2 p01 = __half22float2(*reinterpret_cast<__half2*>(&e01));
            float2 p23 = __half22float2(*reinterpret_cast<__half2*>(&e23));
            rowpart[mt][0] += p01.x + p01.y;
            rowpart[mt][1] += p23.x + p23.y;
        }
    }
    __syncthreads();

    // coalesced streaming stores: 128 rows x 16 uint4 segments
#pragma unroll
    for (int i = 0; i < 8; i++) {
        int idx = t + i * 256;
        int row = idx >> 4, seg = idx & 15;
        uint4 v = *reinterpret_cast<const uint4*>(Ss + row * 136 + seg * 8);
        st_cs_u4(Se + (size_t)(m0 + row) * L_ + n0 + seg * 8, v);
    }

#pragma unroll
    for (int mt = 0; mt < 4; mt++) {
#pragma unroll
        for (int half = 0; half < 2; half++) {
            float v = rowpart[mt][half];
            v += __shfl_xor_sync(0xffffffffu, v, 1);
            v += __shfl_xor_sync(0xffffffffu, v, 2);
            if (tg == 0)
                red[warpN * 128 + warpM * 64 + mt * 16 + gid + half * 8] = v;
        }
    }
    __syncthreads();
    if (t < 128) {
        float s = red[t] + red[128 + t] + red[256 + t] + red[384 + t];
        g_psum[((size_t)bh * L_ + m0 + t) * 16 + blockIdx.y] = s;
    }
}

// ---------------------------------------------------------------------------
// Kernel 3: AV + normalize write-back, 64-row stripes (R16 winner, unchanged).
// grid (32, 1, 32), 256 threads, 3 CTAs/SM.
// ---------------------------------------------------------------------------
static constexpr int AV_A = 64 * 40;
static constexpr int AV_B = 64 * 40;
static constexpr int AV_HB = (3 * AV_A + 3 * AV_B) * 2;   // 30720 bytes
static constexpr int AV_SMEM = AV_HB + 64 * 4;            // 30976 B

__global__ void __launch_bounds__(256, 3) av_mma(float* __restrict__ attn,
                                                 float* __restrict__ out)
{
    extern __shared__ char smc[];
    __half* As = reinterpret_cast<__half*>(smc);
    __half* Vs = As + 3 * AV_A;
    float* rowinv = reinterpret_cast<float*>(smc + AV_HB);
    uint32_t sA = smem_u32(As), sV = smem_u32(Vs);

    int t = threadIdx.x;
    int lane = t & 31, wid = t >> 5;
    int gid = lane >> 2, tg = lane & 3;
    int warpM = wid >> 1, warpN = wid & 1;
    int m0 = blockIdx.x * 64, bh = blockIdx.z;
    int bb = bh >> 3, h = bh & 7;

    const __half* Se = g_se + (size_t)bh * L_ * L_;
    const __half* Vt = g_vth + (size_t)bh * E_ * L_;
    float* A = attn + (size_t)bh * L_ * L_;

    float acc[4][4] = {};

    auto stage = [&](int kt, int buf) {
        int k0 = kt * 32;
        {
            int row = t >> 2, g = t & 3;
            cp16(sA + (buf * AV_A + row * 40 + g * 8) * 2,
                 Se + (size_t)(m0 + row) * L_ + k0 + g * 8);
        }
        {
            int row = t >> 2, g = t & 3;
            cp16(sV + (buf * AV_B + row * 40 + g * 8) * 2,
                 Vt + (size_t)row * L_ + k0 + g * 8);
        }
    };

    const int NIT = L_ / 32;                  // 64
    stage(0, 0); CP_COMMIT();
    stage(1, 1); CP_COMMIT();

    if (t < 64) {
        const float* pp = g_psum + ((size_t)bh * L_ + m0 + t) * 16;
        float s = 0.f;
#pragma unroll
        for (int j = 0; j < 16; j++) s += pp[j];
        rowinv[t] = 1.0f / s;
    }

    for (int kt = 0; kt < NIT; kt++) {
        __syncthreads();
        if (kt + 2 < NIT) { stage(kt + 2, (kt + 2) % 3); CP_COMMIT(); CP_WAIT(2); }
        else if (kt + 1 < NIT) { CP_WAIT(1); }
        else { CP_WAIT(0); }
        __syncthreads();

        int p = kt % 3;
        const __half* Ab = As + p * AV_A;
        const __half* Vb = Vs + p * AV_B;

        {
            int k0 = kt * 32;
            int row = t >> 2, g = t & 3;
            uint4 hv = *reinterpret_cast<const uint4*>(Ab + row * 40 + g * 8);
            float s = rowinv[row];
            float2 f0 = __half22float2(*reinterpret_cast<__half2*>(&hv.x));
            float2 f1 = __half22float2(*reinterpret_cast<__half2*>(&hv.y));
            float2 f2 = __half22float2(*reinterpret_cast<__half2*>(&hv.z));
            float2 f3 = __half22float2(*reinterpret_cast<__half2*>(&hv.w));
            st_cs4(A + (size_t)(m0 + row) * L_ + k0 + g * 8,
                   make_float4(f0.x * s, f0.y * s, f1.x * s, f1.y * s));
            st_cs4(A + (size_t)(m0 + row) * L_ + k0 + g * 8 + 4,
                   make_float4(f2.x * s, f2.y * s, f3.x * s, f3.y * s));
        }

#pragma unroll
        for (int ks = 0; ks < 2; ks++) {
            int kk = ks * 16;
            uint32_t a[4], b[4][2];
            {
                int row = warpM * 16 + gid;
                a[0] = *reinterpret_cast<const uint32_t*>(Ab + row * 40 + kk + tg * 2);
                a[1] = *reinterpret_cast<const uint32_t*>(Ab + (row + 8) * 40 + kk + tg * 2);
                a[2] = *reinterpret_cast<const uint32_t*>(Ab + row * 40 + kk + tg * 2 + 8);
                a[3] = *reinterpret_cast<const uint32_t*>(Ab + (row + 8) * 40 + kk + tg * 2 + 8);
            }
#pragma unroll
            for (int nt = 0; nt < 4; nt++) {
                int n = warpN * 32 + nt * 8 + gid;
                b[nt][0] = *reinterpret_cast<const uint32_t*>(Vb + n * 40 + kk + tg * 2);
                b[nt][1] = *reinterpret_cast<const uint32_t*>(Vb + n * 40 + kk + tg * 2 + 8);
            }
#pragma unroll
            for (int nt = 0; nt < 4; nt++)
                mma_f16(acc[nt], a, b[nt]);
        }
    }

    {
        int rloc = warpM * 16 + gid;
        int r = m0 + rloc;
        float s0 = rowinv[rloc], s1 = rowinv[rloc + 8];
#pragma unroll
        for (int nt = 0; nt < 4; nt++) {
            int cc = warpN * 32 + nt * 8 + tg * 2;
            *reinterpret_cast<float2*>(out + ((size_t)(bb * L_ + r)) * D_ + h * 64 + cc) =
                make_float2(acc[nt][0] * s0, acc[nt][1] * s0);
            *reinterpret_cast<float2*>(out + ((size_t)(bb * L_ + r + 8)) * D_ + h * 64 + cc) =
                make_float2(acc[nt][2] * s1, acc[nt][3] * s1);
        }
    }
}

// ---------------------------------------------------------------------------
extern "C" void kernel_launch(void* const* d_in, const int* in_sizes, int n_in,
                              void* d_out, int out_size)
{
    const float* queries = (const float*)d_in[0];
    const float* keys    = (const float*)d_in[1];
    const float* values  = (const float*)d_in[2];
    const float* Wq      = (const float*)d_in[3];
    const float* bq      = (const float*)d_in[4];
    const float* Wk      = (const float*)d_in[5];
    const float* bk      = (const float*)d_in[6];
    const float* Wv      = (const float*)d_in[7];
    const float* bv      = (const float*)d_in[8];

    float* out  = (float*)d_out;
    float* attn = out + (size_t)B_ * L_ * D_;   // tuple order: (out, attn)

    static bool attr_set = false;
    if (!attr_set) {
        cudaFuncSetAttribute(proj_qk16,  cudaFuncAttributeMaxDynamicSharedMemorySize, PQK_SMEM);
        cudaFuncSetAttribute(proj_v,     cudaFuncAttributeMaxDynamicSharedMemorySize, PJ_SMEM);
        cudaFuncSetAttribute(scores_mma, cudaFuncAttributeMaxDynamicSharedMemorySize, S_SMEM);
        cudaFuncSetAttribute(av_mma,     cudaFuncAttributeMaxDynamicSharedMemorySize, AV_SMEM);
        attr_set = true;
    }

    cvt_x<<<dim3((B_ * L_ * D_) / (256 * 4), 2), 256>>>(queries, keys);
    cvt_wt<<<dim3(16, 16, 2), 256>>>(Wq, Wk);
    proj_v<<<dim3((B_ * L_) / 128, D_ / 128), 256, PJ_SMEM>>>(values, Wv, bv);
    proj_qk16<<<dim3((B_ * L_) / 128, D_ / 128, 2), 256, PQK_SMEM>>>(bq, bk);
    scores_mma<<<dim3(L_ / 128, L_ / 128, B_ * H_), 256, S_SMEM>>>();
    av_mma<<<dim3(L_ / 64, 1, B_ * H_), 256, AV_SMEM>>>(attn, out);
}